// round 2
// baseline (speedup 1.0000x reference)
#include <cuda_runtime.h>
#include <cstdint>

// Problem constants (match reference_code)
#define VOC_SIZE 1000000
#define EMBED_DIM 64
#define N_UPD 262144
#define N_Q (4096 * 200)  // 819200 query rows

// Scratch: sparse delta table + touched-row flags. __device__ globals are the
// sanctioned allocation-free scratch. Both persist across graph replays, but
// K1 re-zeros exactly the rows that K2 re-touches (same indices every replay),
// so every replay is deterministic.
__device__ float g_delta[(size_t)VOC_SIZE * EMBED_DIM];   // 256 MB
__device__ unsigned char g_flag[VOC_SIZE];                // 1 MB

// NOTE: JAX demotes int64->int32 by default, so indices/qs are int32 buffers.

// K1: zero the delta rows that will be scatter-added, set flags.
// One thread per float4 (16 threads per row). Duplicate indices -> duplicate
// zero-writes, harmless.
__global__ void zero_delta_kernel(const int* __restrict__ indices) {
    int t = blockIdx.x * blockDim.x + threadIdx.x;   // 0 .. N_UPD*16-1
    int i = t >> 4;
    int j = t & 15;
    int row = indices[i];
    float4 z = make_float4(0.f, 0.f, 0.f, 0.f);
    *reinterpret_cast<float4*>(&g_delta[(size_t)row * EMBED_DIM + j * 4]) = z;
    if (j == 0) g_flag[row] = 1;
}

// K2: scatter-add emb_update into delta with vector reduction atomics
// (red.global.add.v4.f32, sm_90+). No return value needed -> REDG path.
__global__ void scatter_add_kernel(const int* __restrict__ indices,
                                   const float* __restrict__ upd) {
    int t = blockIdx.x * blockDim.x + threadIdx.x;   // 0 .. N_UPD*16-1
    int i = t >> 4;
    int j = t & 15;
    int row = indices[i];
    float4 v = *reinterpret_cast<const float4*>(&upd[(size_t)i * EMBED_DIM + j * 4]);
    float* p = &g_delta[(size_t)row * EMBED_DIM + j * 4];
    asm volatile("red.global.add.v4.f32 [%0], {%1, %2, %3, %4};"
                 :: "l"(p), "f"(v.x), "f"(v.y), "f"(v.z), "f"(v.w)
                 : "memory");
}

// K3: gather. out[i] = kernel[qs[i]] + (touched ? delta[qs[i]] : 0).
// 16 consecutive threads cover one 256B row -> coalesced 2-line reads/writes.
__global__ void gather_kernel(const float* __restrict__ table,
                              const int* __restrict__ qs,
                              float* __restrict__ out) {
    int t = blockIdx.x * blockDim.x + threadIdx.x;   // 0 .. N_Q*16-1
    int i = t >> 4;
    int j = t & 15;
    int row = qs[i];
    size_t off = (size_t)row * EMBED_DIM + j * 4;
    float4 v = __ldg(reinterpret_cast<const float4*>(&table[off]));
    if (g_flag[row]) {
        float4 d = *reinterpret_cast<const float4*>(&g_delta[off]);
        v.x += d.x; v.y += d.y; v.z += d.z; v.w += d.w;
    }
    *reinterpret_cast<float4*>(&out[(size_t)i * EMBED_DIM + j * 4]) = v;
}

extern "C" void kernel_launch(void* const* d_in, const int* in_sizes, int n_in,
                              void* d_out, int out_size) {
    // metadata order: kernel (f32), indices (i32), emb_update (f32), qs (i32)
    const float* table   = (const float*)d_in[0];
    const int*   indices = (const int*)d_in[1];
    const float* upd     = (const float*)d_in[2];
    const int*   qs      = (const int*)d_in[3];
    float* out = (float*)d_out;

    // N_UPD*16 = 4,194,304 threads = 16384 blocks of 256 (exact)
    zero_delta_kernel<<<(N_UPD * 16) / 256, 256>>>(indices);
    scatter_add_kernel<<<(N_UPD * 16) / 256, 256>>>(indices, upd);
    // N_Q*16 = 13,107,200 threads = 51200 blocks of 256 (exact)
    gather_kernel<<<(N_Q * 16) / 256, 256>>>(table, qs, out);
}

// round 4
// speedup vs baseline: 1.1733x; 1.1733x over previous
#include <cuda_runtime.h>
#include <cstdint>

// Problem constants (match reference_code)
#define VOC_SIZE 1000000
#define EMBED_DIM 64
#define N_UPD 262144
#define N_Q (4096 * 200)  // 819200 query rows

// Scratch: sparse delta table + touched-row flags (allocation-free __device__
// globals). K1 re-zeros exactly the rows K2 re-touches every replay, so each
// graph replay is deterministic.
__device__ float g_delta[(size_t)VOC_SIZE * EMBED_DIM];   // 256 MB
__device__ unsigned char g_flag[VOC_SIZE];                // 1 MB

// 32-byte table load with L2 evict_last (ptxas requires .v4.b64 width for the
// evict_last modifier on sm_103a). Table rows are re-read by duplicate
// queries; bias them to stay resident in L2.
__device__ __forceinline__ void ldg_evict_last_32B(const float* p,
                                                   float4& a, float4& b) {
    unsigned long long x, y, z, w;
    asm("ld.global.nc.L2::evict_last.v4.b64 {%0,%1,%2,%3}, [%4];"
        : "=l"(x), "=l"(y), "=l"(z), "=l"(w) : "l"(p));
    a.x = __uint_as_float((unsigned)(x));
    a.y = __uint_as_float((unsigned)(x >> 32));
    a.z = __uint_as_float((unsigned)(y));
    a.w = __uint_as_float((unsigned)(y >> 32));
    b.x = __uint_as_float((unsigned)(z));
    b.y = __uint_as_float((unsigned)(z >> 32));
    b.z = __uint_as_float((unsigned)(w));
    b.w = __uint_as_float((unsigned)(w >> 32));
}

// K1: zero the delta rows that will be scatter-added, set flags.
// 8 threads per row, 2x 16B stores each (ILP; K1 is issue-bound, not BW-bound).
__global__ void zero_delta_kernel(const int* __restrict__ indices) {
    int t = blockIdx.x * blockDim.x + threadIdx.x;   // 0 .. N_UPD*8-1
    int i = t >> 3;
    int j = t & 7;
    int row = indices[i];
    float4 z = make_float4(0.f, 0.f, 0.f, 0.f);
    float4* p = reinterpret_cast<float4*>(&g_delta[(size_t)row * EMBED_DIM + j * 8]);
    p[0] = z;
    p[1] = z;
    if (j == 0) g_flag[row] = 1;
}

// K2: scatter-add emb_update into delta with vector reduction atomics
// (red.global.add.v4.f32). Duplicate indices accumulate in the L2 atomic ALUs.
__global__ void scatter_add_kernel(const int* __restrict__ indices,
                                   const float* __restrict__ upd) {
    int t = blockIdx.x * blockDim.x + threadIdx.x;   // 0 .. N_UPD*16-1
    int i = t >> 4;
    int j = t & 15;
    int row = indices[i];
    float4 v = *reinterpret_cast<const float4*>(&upd[(size_t)i * EMBED_DIM + j * 4]);
    float* p = &g_delta[(size_t)row * EMBED_DIM + j * 4];
    asm volatile("red.global.add.v4.f32 [%0], {%1, %2, %3, %4};"
                 :: "l"(p), "f"(v.x), "f"(v.y), "f"(v.z), "f"(v.w)
                 : "memory");
}

// K3: gather. out[i] = table[qs[i]] + (touched ? delta[qs[i]] : 0).
// 8 threads per 256B row, 32B per thread; each thread handles two query rows
// (i, i+N_Q/2) for high MLP. Table reads use L2 evict_last; output streams
// past L2 (__stcs) so it doesn't evict reusable table rows.
__global__ void gather_kernel(const float* __restrict__ table,
                              const int* __restrict__ qs,
                              float* __restrict__ out) {
    int t = blockIdx.x * blockDim.x + threadIdx.x;   // 0 .. N_Q*4-1
    int i0 = t >> 3;
    int j  = t & 7;
    int i1 = i0 + (N_Q / 2);

    int r0 = qs[i0];
    int r1 = qs[i1];
    size_t o0 = (size_t)r0 * EMBED_DIM + j * 8;
    size_t o1 = (size_t)r1 * EMBED_DIM + j * 8;

    float4 a0, b0, a1, b1;
    ldg_evict_last_32B(&table[o0], a0, b0);
    ldg_evict_last_32B(&table[o1], a1, b1);
    unsigned char f0 = g_flag[r0];
    unsigned char f1 = g_flag[r1];

    if (f0) {
        float4 da = __ldg(reinterpret_cast<const float4*>(&g_delta[o0]));
        float4 db = __ldg(reinterpret_cast<const float4*>(&g_delta[o0 + 4]));
        a0.x += da.x; a0.y += da.y; a0.z += da.z; a0.w += da.w;
        b0.x += db.x; b0.y += db.y; b0.z += db.z; b0.w += db.w;
    }
    if (f1) {
        float4 da = __ldg(reinterpret_cast<const float4*>(&g_delta[o1]));
        float4 db = __ldg(reinterpret_cast<const float4*>(&g_delta[o1 + 4]));
        a1.x += da.x; a1.y += da.y; a1.z += da.z; a1.w += da.w;
        b1.x += db.x; b1.y += db.y; b1.z += db.z; b1.w += db.w;
    }

    size_t q0 = (size_t)i0 * EMBED_DIM + j * 8;
    size_t q1 = (size_t)i1 * EMBED_DIM + j * 8;
    __stcs(reinterpret_cast<float4*>(&out[q0]), a0);
    __stcs(reinterpret_cast<float4*>(&out[q0 + 4]), b0);
    __stcs(reinterpret_cast<float4*>(&out[q1]), a1);
    __stcs(reinterpret_cast<float4*>(&out[q1 + 4]), b1);
}

extern "C" void kernel_launch(void* const* d_in, const int* in_sizes, int n_in,
                              void* d_out, int out_size) {
    // metadata order: kernel (f32), indices (i32), emb_update (f32), qs (i32)
    const float* table   = (const float*)d_in[0];
    const int*   indices = (const int*)d_in[1];
    const float* upd     = (const float*)d_in[2];
    const int*   qs      = (const int*)d_in[3];
    float* out = (float*)d_out;

    // K1: N_UPD*8 = 2,097,152 threads = 8192 blocks of 256 (exact)
    zero_delta_kernel<<<(N_UPD * 8) / 256, 256>>>(indices);
    // K2: N_UPD*16 = 4,194,304 threads = 16384 blocks of 256 (exact)
    scatter_add_kernel<<<(N_UPD * 16) / 256, 256>>>(indices, upd);
    // K3: N_Q*4 = 3,276,800 threads = 12800 blocks of 256 (exact)
    gather_kernel<<<(N_Q * 4) / 256, 256>>>(table, qs, out);
}

// round 5
// speedup vs baseline: 1.2216x; 1.0412x over previous
#include <cuda_runtime.h>
#include <cstdint>

// Problem constants (match reference_code)
#define VOC_SIZE 1000000
#define EMBED_DIM 64
#define N_UPD 262144
#define N_Q (4096 * 200)  // 819200 query rows

// Scratch: sparse delta table + touched-row flags (allocation-free __device__
// globals). K1 re-zeros exactly the rows K2 re-touches every replay, so each
// graph replay is deterministic.
__device__ float g_delta[(size_t)VOC_SIZE * EMBED_DIM];   // 256 MB
__device__ unsigned char g_flag[VOC_SIZE];                // 1 MB

typedef unsigned long long u64;

// 32-byte table load with L2 evict_last (sm_103a: modifier requires
// .v8.b32 / .v4.b64 width). Duplicate queries re-read table rows; bias them
// to stay resident in L2.
__device__ __forceinline__ void ldg_evict_last_32B(const float* p,
                                                   u64& x, u64& y, u64& z, u64& w) {
    asm("ld.global.nc.L2::evict_last.v4.b64 {%0,%1,%2,%3}, [%4];"
        : "=l"(x), "=l"(y), "=l"(z), "=l"(w) : "l"(p));
}

// 32-byte streaming store (cs = evict-first both levels): output is written
// once and never re-read; keep it from evicting reusable table rows.
__device__ __forceinline__ void stg_cs_32B(float* p, u64 x, u64 y, u64 z, u64 w) {
    asm volatile("st.global.cs.v4.b64 [%0], {%1,%2,%3,%4};"
                 :: "l"(p), "l"(x), "l"(y), "l"(z), "l"(w) : "memory");
}

__device__ __forceinline__ u64 pack2(float lo, float hi) {
    return ((u64)__float_as_uint(hi) << 32) | (u64)__float_as_uint(lo);
}

// K1: zero the delta rows that will be scatter-added, set flags.
// 8 threads per row, ONE 32B store each -> fully contiguous 256B per row
// across 8 lanes (max bytes per L1 wavefront), half the instructions of the
// float4 variant.
__global__ void zero_delta_kernel(const int* __restrict__ indices) {
    int t = blockIdx.x * blockDim.x + threadIdx.x;   // 0 .. N_UPD*8-1
    int i = t >> 3;
    int j = t & 7;
    int row = indices[i];
    float* p = &g_delta[(size_t)row * EMBED_DIM + j * 8];
    u64 z = 0ULL;
    asm volatile("st.global.v4.b64 [%0], {%1,%1,%1,%1};"
                 :: "l"(p), "l"(z) : "memory");
    if (j == 0) g_flag[row] = 1;
}

// K2: scatter-add emb_update into delta with vector reduction atomics
// (red.global.add.v4.f32). Duplicate indices accumulate in the L2 atomic ALUs.
__global__ void scatter_add_kernel(const int* __restrict__ indices,
                                   const float* __restrict__ upd) {
    int t = blockIdx.x * blockDim.x + threadIdx.x;   // 0 .. N_UPD*16-1
    int i = t >> 4;
    int j = t & 15;
    int row = indices[i];
    float4 v = *reinterpret_cast<const float4*>(&upd[(size_t)i * EMBED_DIM + j * 4]);
    float* p = &g_delta[(size_t)row * EMBED_DIM + j * 4];
    asm volatile("red.global.add.v4.f32 [%0], {%1, %2, %3, %4};"
                 :: "l"(p), "f"(v.x), "f"(v.y), "f"(v.z), "f"(v.w)
                 : "memory");
}

// K3: gather. out[i] = table[qs[i]] + (touched ? delta[qs[i]] : 0).
// 8 threads per 256B row, 32B per thread; each thread handles two query rows
// (i, i+N_Q/2) for MLP. Table reads: L2 evict_last. Output: 32B streaming
// stores. Data stays in 64-bit regs on the unflagged (~77%) fast path.
__global__ void gather_kernel(const float* __restrict__ table,
                              const int* __restrict__ qs,
                              float* __restrict__ out) {
    int t = blockIdx.x * blockDim.x + threadIdx.x;   // 0 .. N_Q*4-1
    int i0 = t >> 3;
    int j  = t & 7;
    int i1 = i0 + (N_Q / 2);

    int r0 = qs[i0];
    int r1 = qs[i1];
    size_t o0 = (size_t)r0 * EMBED_DIM + j * 8;
    size_t o1 = (size_t)r1 * EMBED_DIM + j * 8;

    u64 x0, y0, z0, w0, x1, y1, z1, w1;
    ldg_evict_last_32B(&table[o0], x0, y0, z0, w0);
    ldg_evict_last_32B(&table[o1], x1, y1, z1, w1);
    unsigned char f0 = g_flag[r0];
    unsigned char f1 = g_flag[r1];

    if (f0) {
        float4 da = __ldg(reinterpret_cast<const float4*>(&g_delta[o0]));
        float4 db = __ldg(reinterpret_cast<const float4*>(&g_delta[o0 + 4]));
        x0 = pack2(__uint_as_float((unsigned)x0) + da.x, __uint_as_float((unsigned)(x0 >> 32)) + da.y);
        y0 = pack2(__uint_as_float((unsigned)y0) + da.z, __uint_as_float((unsigned)(y0 >> 32)) + da.w);
        z0 = pack2(__uint_as_float((unsigned)z0) + db.x, __uint_as_float((unsigned)(z0 >> 32)) + db.y);
        w0 = pack2(__uint_as_float((unsigned)w0) + db.z, __uint_as_float((unsigned)(w0 >> 32)) + db.w);
    }
    if (f1) {
        float4 da = __ldg(reinterpret_cast<const float4*>(&g_delta[o1]));
        float4 db = __ldg(reinterpret_cast<const float4*>(&g_delta[o1 + 4]));
        x1 = pack2(__uint_as_float((unsigned)x1) + da.x, __uint_as_float((unsigned)(x1 >> 32)) + da.y);
        y1 = pack2(__uint_as_float((unsigned)y1) + da.z, __uint_as_float((unsigned)(y1 >> 32)) + da.w);
        z1 = pack2(__uint_as_float((unsigned)z1) + db.x, __uint_as_float((unsigned)(z1 >> 32)) + db.y);
        w1 = pack2(__uint_as_float((unsigned)w1) + db.z, __uint_as_float((unsigned)(w1 >> 32)) + db.w);
    }

    stg_cs_32B(&out[(size_t)i0 * EMBED_DIM + j * 8], x0, y0, z0, w0);
    stg_cs_32B(&out[(size_t)i1 * EMBED_DIM + j * 8], x1, y1, z1, w1);
}

extern "C" void kernel_launch(void* const* d_in, const int* in_sizes, int n_in,
                              void* d_out, int out_size) {
    // metadata order: kernel (f32), indices (i32), emb_update (f32), qs (i32)
    const float* table   = (const float*)d_in[0];
    const int*   indices = (const int*)d_in[1];
    const float* upd     = (const float*)d_in[2];
    const int*   qs      = (const int*)d_in[3];
    float* out = (float*)d_out;

    // K1: N_UPD*8 = 2,097,152 threads = 8192 blocks of 256 (exact)
    zero_delta_kernel<<<(N_UPD * 8) / 256, 256>>>(indices);
    // K2: N_UPD*16 = 4,194,304 threads = 16384 blocks of 256 (exact)
    scatter_add_kernel<<<(N_UPD * 16) / 256, 256>>>(indices, upd);
    // K3: N_Q*4 = 3,276,800 threads = 12800 blocks of 256 (exact)
    gather_kernel<<<(N_Q * 4) / 256, 256>>>(table, qs, out);
}

// round 6
// speedup vs baseline: 1.2816x; 1.0491x over previous
#include <cuda_runtime.h>
#include <cstdint>

// Problem constants (match reference_code)
#define VOC_SIZE 1000000
#define EMBED_DIM 64
#define N_UPD 262144
#define N_Q (4096 * 200)  // 819200 query rows

// Scratch (allocation-free __device__ globals).
// g_delta: sparse per-row accumulator. g_count: per-row update multiplicity,
// fully re-zeroed every replay (M0), so each graph replay is deterministic:
//   count==1 rows are fully overwritten by a plain store (no zero needed),
//   count>1 rows are zeroed (K2b) then atomically accumulated (K2c).
__device__ float g_delta[(size_t)VOC_SIZE * EMBED_DIM];   // 256 MB
__device__ int   g_count[1 << 20];                        // 4 MB (padded)

typedef unsigned long long u64;

// 32-byte table load with L2 evict_last (sm_103a: modifier requires
// .v8.b32 / .v4.b64 width). Duplicate queries re-read table rows; bias them
// to stay resident in L2.
__device__ __forceinline__ void ldg_evict_last_32B(const float* p,
                                                   u64& x, u64& y, u64& z, u64& w) {
    asm("ld.global.nc.L2::evict_last.v4.b64 {%0,%1,%2,%3}, [%4];"
        : "=l"(x), "=l"(y), "=l"(z), "=l"(w) : "l"(p));
}

__device__ __forceinline__ void ldg_32B(const float* p,
                                        u64& x, u64& y, u64& z, u64& w) {
    asm("ld.global.nc.v4.b64 {%0,%1,%2,%3}, [%4];"
        : "=l"(x), "=l"(y), "=l"(z), "=l"(w) : "l"(p));
}

__device__ __forceinline__ void stg_32B(float* p, u64 x, u64 y, u64 z, u64 w) {
    asm volatile("st.global.v4.b64 [%0], {%1,%2,%3,%4};"
                 :: "l"(p), "l"(x), "l"(y), "l"(z), "l"(w) : "memory");
}

// Streaming store (evict-first): output is written once and never re-read.
__device__ __forceinline__ void stg_cs_32B(float* p, u64 x, u64 y, u64 z, u64 w) {
    asm volatile("st.global.cs.v4.b64 [%0], {%1,%2,%3,%4};"
                 :: "l"(p), "l"(x), "l"(y), "l"(z), "l"(w) : "memory");
}

__device__ __forceinline__ u64 pack2(float lo, float hi) {
    return ((u64)__float_as_uint(hi) << 32) | (u64)__float_as_uint(lo);
}
__device__ __forceinline__ float f_lo(u64 v) { return __uint_as_float((unsigned)v); }
__device__ __forceinline__ float f_hi(u64 v) { return __uint_as_float((unsigned)(v >> 32)); }

// M0: full contiguous zero of the count array (4 MB). 131072 threads x 32B.
__global__ void zero_count_kernel() {
    int t = blockIdx.x * blockDim.x + threadIdx.x;
    u64 z = 0ULL;
    asm volatile("st.global.v4.b64 [%0], {%1,%1,%1,%1};"
                 :: "l"(&g_count[t * 8]), "l"(z) : "memory");
}

// K2a: per-row multiplicity. Two independent updates per thread for MLP.
__global__ void count_kernel(const int* __restrict__ indices) {
    int t = blockIdx.x * blockDim.x + threadIdx.x;   // 0 .. N_UPD/2-1
    int r0 = indices[t];
    int r1 = indices[t + N_UPD / 2];
    atomicAdd(&g_count[r0], 1);
    atomicAdd(&g_count[r1], 1);
}

// K2b: zero delta rows that will receive multiple adds (~13% of updates,
// redundant zeroing by duplicates is harmless). 4 threads/row x 64B.
__global__ void zero_dup_kernel(const int* __restrict__ indices) {
    int t = blockIdx.x * blockDim.x + threadIdx.x;   // 0 .. N_UPD*4-1
    int i = t >> 2;
    int j = t & 3;
    int row = indices[i];
    if (g_count[row] > 1) {
        float* p = &g_delta[(size_t)row * EMBED_DIM + j * 16];
        u64 z = 0ULL;
        asm volatile("st.global.v4.b64 [%0], {%1,%1,%1,%1};"
                     :: "l"(p), "l"(z) : "memory");
        asm volatile("st.global.v4.b64 [%0], {%1,%1,%1,%1};"
                     :: "l"(p + 8), "l"(z) : "memory");
    }
}

// K2c: scatter. Singleton rows (87%): plain 32B store (full-row overwrite,
// no zeroing needed). Dup rows: vector reduction atomics onto zeroed base.
__global__ void scatter_kernel(const int* __restrict__ indices,
                               const float* __restrict__ upd) {
    int t = blockIdx.x * blockDim.x + threadIdx.x;   // 0 .. N_UPD*8-1
    int i = t >> 3;
    int j = t & 7;
    int row = indices[i];
    u64 x, y, z, w;
    ldg_32B(&upd[(size_t)i * EMBED_DIM + j * 8], x, y, z, w);
    int c = g_count[row];
    float* p = &g_delta[(size_t)row * EMBED_DIM + j * 8];
    if (c == 1) {
        stg_32B(p, x, y, z, w);
    } else {
        asm volatile("red.global.add.v4.f32 [%0], {%1,%2,%3,%4};"
                     :: "l"(p), "f"(f_lo(x)), "f"(f_hi(x)), "f"(f_lo(y)), "f"(f_hi(y))
                     : "memory");
        asm volatile("red.global.add.v4.f32 [%0], {%1,%2,%3,%4};"
                     :: "l"(p + 4), "f"(f_lo(z)), "f"(f_hi(z)), "f"(f_lo(w)), "f"(f_hi(w))
                     : "memory");
    }
}

// K3: gather. out[i] = table[qs[i]] + (count[qs[i]]>0 ? delta[qs[i]] : 0).
// 8 threads per 256B row, 32B per thread; each thread handles two query rows
// (i, i+N_Q/2) for MLP. Table reads: L2 evict_last. Output: streaming stores.
__global__ void gather_kernel(const float* __restrict__ table,
                              const int* __restrict__ qs,
                              float* __restrict__ out) {
    int t = blockIdx.x * blockDim.x + threadIdx.x;   // 0 .. N_Q*4-1
    int i0 = t >> 3;
    int j  = t & 7;
    int i1 = i0 + (N_Q / 2);

    int r0 = qs[i0];
    int r1 = qs[i1];
    size_t o0 = (size_t)r0 * EMBED_DIM + j * 8;
    size_t o1 = (size_t)r1 * EMBED_DIM + j * 8;

    u64 x0, y0, z0, w0, x1, y1, z1, w1;
    ldg_evict_last_32B(&table[o0], x0, y0, z0, w0);
    ldg_evict_last_32B(&table[o1], x1, y1, z1, w1);
    int f0 = g_count[r0];
    int f1 = g_count[r1];

    if (f0) {
        float4 da = __ldg(reinterpret_cast<const float4*>(&g_delta[o0]));
        float4 db = __ldg(reinterpret_cast<const float4*>(&g_delta[o0 + 4]));
        x0 = pack2(f_lo(x0) + da.x, f_hi(x0) + da.y);
        y0 = pack2(f_lo(y0) + da.z, f_hi(y0) + da.w);
        z0 = pack2(f_lo(z0) + db.x, f_hi(z0) + db.y);
        w0 = pack2(f_lo(w0) + db.z, f_hi(w0) + db.w);
    }
    if (f1) {
        float4 da = __ldg(reinterpret_cast<const float4*>(&g_delta[o1]));
        float4 db = __ldg(reinterpret_cast<const float4*>(&g_delta[o1 + 4]));
        x1 = pack2(f_lo(x1) + da.x, f_hi(x1) + da.y);
        y1 = pack2(f_lo(y1) + da.z, f_hi(y1) + da.w);
        z1 = pack2(f_lo(z1) + db.x, f_hi(z1) + db.y);
        w1 = pack2(f_lo(w1) + db.z, f_hi(w1) + db.w);
    }

    stg_cs_32B(&out[(size_t)i0 * EMBED_DIM + j * 8], x0, y0, z0, w0);
    stg_cs_32B(&out[(size_t)i1 * EMBED_DIM + j * 8], x1, y1, z1, w1);
}

extern "C" void kernel_launch(void* const* d_in, const int* in_sizes, int n_in,
                              void* d_out, int out_size) {
    // metadata order: kernel (f32), indices (i32), emb_update (f32), qs (i32)
    const float* table   = (const float*)d_in[0];
    const int*   indices = (const int*)d_in[1];
    const float* upd     = (const float*)d_in[2];
    const int*   qs      = (const int*)d_in[3];
    float* out = (float*)d_out;

    // M0: (1<<20) ints / 8 per thread = 131072 threads = 512 blocks (exact)
    zero_count_kernel<<<512, 256>>>();
    // K2a: N_UPD/2 threads = 512 blocks (exact)
    count_kernel<<<512, 256>>>(indices);
    // K2b: N_UPD*4 threads = 4096 blocks (exact)
    zero_dup_kernel<<<4096, 256>>>(indices);
    // K2c: N_UPD*8 threads = 8192 blocks (exact)
    scatter_kernel<<<8192, 256>>>(indices, upd);
    // K3: N_Q*4 threads = 12800 blocks (exact)
    gather_kernel<<<12800, 256>>>(table, qs, out);
}

// round 7
// speedup vs baseline: 1.3549x; 1.0572x over previous
#include <cuda_runtime.h>
#include <cstdint>

// Problem constants (match reference_code)
#define VOC_SIZE 1000000
#define EMBED_DIM 64
#define N_UPD 262144
#define N_Q (4096 * 200)  // 819200 query rows

// Scratch (allocation-free __device__ globals).
// g_count: per-row update multiplicity, fully re-zeroed every replay.
// g_src:   for count==1 rows, the index of the unique update (single writer);
//          garbage for dup rows (unused there).
// g_delta: accumulator used ONLY for dup rows (count>1): zeroed then
//          atomically accumulated each replay -> deterministic.
__device__ float g_delta[(size_t)VOC_SIZE * EMBED_DIM];   // 256 MB
__device__ int   g_count[1 << 20];                        // 4 MB (padded)
__device__ int   g_src[1 << 20];                          // 4 MB

typedef unsigned long long u64;

// 32-byte table load with L2 evict_last (sm_103a: modifier requires
// .v8.b32 / .v4.b64 width). Duplicate queries re-read table rows; bias them
// to stay resident in L2.
__device__ __forceinline__ void ldg_evict_last_32B(const float* p,
                                                   u64& x, u64& y, u64& z, u64& w) {
    asm("ld.global.nc.L2::evict_last.v4.b64 {%0,%1,%2,%3}, [%4];"
        : "=l"(x), "=l"(y), "=l"(z), "=l"(w) : "l"(p));
}

__device__ __forceinline__ void ldg_32B(const float* p,
                                        u64& x, u64& y, u64& z, u64& w) {
    asm("ld.global.nc.v4.b64 {%0,%1,%2,%3}, [%4];"
        : "=l"(x), "=l"(y), "=l"(z), "=l"(w) : "l"(p));
}

// Streaming store (evict-first): output is written once and never re-read.
__device__ __forceinline__ void stg_cs_32B(float* p, u64 x, u64 y, u64 z, u64 w) {
    asm volatile("st.global.cs.v4.b64 [%0], {%1,%2,%3,%4};"
                 :: "l"(p), "l"(x), "l"(y), "l"(z), "l"(w) : "memory");
}

__device__ __forceinline__ u64 pack2(float lo, float hi) {
    return ((u64)__float_as_uint(hi) << 32) | (u64)__float_as_uint(lo);
}
__device__ __forceinline__ float f_lo(u64 v) { return __uint_as_float((unsigned)v); }
__device__ __forceinline__ float f_hi(u64 v) { return __uint_as_float((unsigned)(v >> 32)); }

// M0: full contiguous zero of the count array (4 MB). 131072 threads x 32B.
__global__ void zero_count_kernel() {
    int t = blockIdx.x * blockDim.x + threadIdx.x;
    u64 z = 0ULL;
    asm volatile("st.global.v4.b64 [%0], {%1,%1,%1,%1};"
                 :: "l"(&g_count[t * 8]), "l"(z) : "memory");
}

// K2a: per-row multiplicity + source index. Two independent updates per
// thread for MLP. g_src races on dup rows only, where it's never read.
__global__ void count_kernel(const int* __restrict__ indices) {
    int t = blockIdx.x * blockDim.x + threadIdx.x;   // 0 .. N_UPD/2-1
    int i1 = t + N_UPD / 2;
    int r0 = indices[t];
    int r1 = indices[i1];
    atomicAdd(&g_count[r0], 1);
    atomicAdd(&g_count[r1], 1);
    g_src[r0] = t;
    g_src[r1] = i1;
}

// K2b: zero delta rows that will receive multiple adds (~13% of updates;
// redundant zeroing by duplicates is harmless). 8 threads/row x 32B.
__global__ void zero_dup_kernel(const int* __restrict__ indices) {
    int t = blockIdx.x * blockDim.x + threadIdx.x;   // 0 .. N_UPD*8-1
    int i = t >> 3;
    int j = t & 7;
    int row = indices[i];
    if (g_count[row] > 1) {
        float* p = &g_delta[(size_t)row * EMBED_DIM + j * 8];
        u64 z = 0ULL;
        asm volatile("st.global.v4.b64 [%0], {%1,%1,%1,%1};"
                     :: "l"(p), "l"(z) : "memory");
    }
}

// K2c: accumulate ONLY dup rows into delta (singletons are served directly
// from upd in the gather). ~13% of updates -> ~26 MB of traffic.
__global__ void scatter_dup_kernel(const int* __restrict__ indices,
                                   const float* __restrict__ upd) {
    int t = blockIdx.x * blockDim.x + threadIdx.x;   // 0 .. N_UPD*8-1
    int i = t >> 3;
    int j = t & 7;
    int row = indices[i];
    if (g_count[row] > 1) {
        u64 x, y, z, w;
        ldg_32B(&upd[(size_t)i * EMBED_DIM + j * 8], x, y, z, w);
        float* p = &g_delta[(size_t)row * EMBED_DIM + j * 8];
        asm volatile("red.global.add.v4.f32 [%0], {%1,%2,%3,%4};"
                     :: "l"(p), "f"(f_lo(x)), "f"(f_hi(x)), "f"(f_lo(y)), "f"(f_hi(y))
                     : "memory");
        asm volatile("red.global.add.v4.f32 [%0], {%1,%2,%3,%4};"
                     :: "l"(p + 4), "f"(f_lo(z)), "f"(f_hi(z)), "f"(f_lo(w)), "f"(f_hi(w))
                     : "memory");
    }
}

// K3: gather. out[i] = table[q] + (count==0 ? 0 : count==1 ? upd[src[q]]
//                                                           : delta[q]).
// 8 threads per 256B row, 32B per thread; each thread handles two query rows
// (i, i+N_Q/2) for MLP. Table reads: L2 evict_last. Output: streaming stores.
__global__ void gather_kernel(const float* __restrict__ table,
                              const int* __restrict__ qs,
                              const float* __restrict__ upd,
                              float* __restrict__ out) {
    int t = blockIdx.x * blockDim.x + threadIdx.x;   // 0 .. N_Q*4-1
    int i0 = t >> 3;
    int j  = t & 7;
    int i1 = i0 + (N_Q / 2);

    int r0 = qs[i0];
    int r1 = qs[i1];
    size_t o0 = (size_t)r0 * EMBED_DIM + j * 8;
    size_t o1 = (size_t)r1 * EMBED_DIM + j * 8;

    u64 x0, y0, z0, w0, x1, y1, z1, w1;
    ldg_evict_last_32B(&table[o0], x0, y0, z0, w0);
    ldg_evict_last_32B(&table[o1], x1, y1, z1, w1);
    int c0 = g_count[r0];
    int c1 = g_count[r1];

    if (c0) {
        const float* dp = (c0 == 1)
            ? &upd[(size_t)g_src[r0] * EMBED_DIM + j * 8]
            : &g_delta[o0];
        float4 da = __ldg(reinterpret_cast<const float4*>(dp));
        float4 db = __ldg(reinterpret_cast<const float4*>(dp + 4));
        x0 = pack2(f_lo(x0) + da.x, f_hi(x0) + da.y);
        y0 = pack2(f_lo(y0) + da.z, f_hi(y0) + da.w);
        z0 = pack2(f_lo(z0) + db.x, f_hi(z0) + db.y);
        w0 = pack2(f_lo(w0) + db.z, f_hi(w0) + db.w);
    }
    if (c1) {
        const float* dp = (c1 == 1)
            ? &upd[(size_t)g_src[r1] * EMBED_DIM + j * 8]
            : &g_delta[o1];
        float4 da = __ldg(reinterpret_cast<const float4*>(dp));
        float4 db = __ldg(reinterpret_cast<const float4*>(dp + 4));
        x1 = pack2(f_lo(x1) + da.x, f_hi(x1) + da.y);
        y1 = pack2(f_lo(y1) + da.z, f_hi(y1) + da.w);
        z1 = pack2(f_lo(z1) + db.x, f_hi(z1) + db.y);
        w1 = pack2(f_lo(w1) + db.z, f_hi(w1) + db.w);
    }

    stg_cs_32B(&out[(size_t)i0 * EMBED_DIM + j * 8], x0, y0, z0, w0);
    stg_cs_32B(&out[(size_t)i1 * EMBED_DIM + j * 8], x1, y1, z1, w1);
}

extern "C" void kernel_launch(void* const* d_in, const int* in_sizes, int n_in,
                              void* d_out, int out_size) {
    // metadata order: kernel (f32), indices (i32), emb_update (f32), qs (i32)
    const float* table   = (const float*)d_in[0];
    const int*   indices = (const int*)d_in[1];
    const float* upd     = (const float*)d_in[2];
    const int*   qs      = (const int*)d_in[3];
    float* out = (float*)d_out;

    // M0: (1<<20) ints / 8 per thread = 131072 threads = 512 blocks (exact)
    zero_count_kernel<<<512, 256>>>();
    // K2a: N_UPD/2 threads = 512 blocks (exact)
    count_kernel<<<512, 256>>>(indices);
    // K2b: N_UPD*8 threads = 8192 blocks (exact)
    zero_dup_kernel<<<8192, 256>>>(indices);
    // K2c: N_UPD*8 threads = 8192 blocks (exact)
    scatter_dup_kernel<<<8192, 256>>>(indices, upd);
    // K3: N_Q*4 threads = 12800 blocks (exact)
    gather_kernel<<<12800, 256>>>(table, qs, upd, out);
}